// round 1
// baseline (speedup 1.0000x reference)
#include <cuda_runtime.h>
#include <math_constants.h>

// Problem shape (fixed by the reference): qkv (B,S,3,H,D) fp32 -> out (B,S,H,D) fp32
#define BB 2
#define SS 2048
#define HH 16
#define DD 64

// Tiling
#define BM 128   // query rows per CTA (= blockDim.x, thread t owns row t)
#define BN 64    // key/value rows staged in smem per tile
#define CH 16    // online-softmax chunk (keeps score regs small, indices static)
#define QS 65    // Q smem row stride (conflict-free per-lane row reads)

__global__ __launch_bounds__(BM) void attn_fwd(
    const float* __restrict__ qkv, float* __restrict__ out)
{
    extern __shared__ float sm[];
    float* qs = sm;                   // BM * QS
    float* ks = sm + BM * QS;         // BN * DD
    float* vs = ks + BN * DD;         // BN * DD

    const int b   = blockIdx.z;
    const int h   = blockIdx.y;
    const int qt  = blockIdx.x;
    const int tid = threadIdx.x;
    const int q0  = qt * BM;
    const int qi  = q0 + tid;         // this thread's query row (always < SS)

    // ---- Load Q row into smem (padded stride 65: (t+d)%32 banks, conflict-free) ----
    {
        const float4* src = reinterpret_cast<const float4*>(
            qkv + (((size_t)(b * SS + qi) * 3 + 0) * HH + h) * DD);
        #pragma unroll
        for (int i = 0; i < DD / 4; i++) {
            float4 t4 = src[i];
            qs[tid * QS + 4 * i + 0] = t4.x;
            qs[tid * QS + 4 * i + 1] = t4.y;
            qs[tid * QS + 4 * i + 2] = t4.z;
            qs[tid * QS + 4 * i + 3] = t4.w;
        }
    }

    float acc[DD];
    #pragma unroll
    for (int d = 0; d < DD; d++) acc[d] = 0.f;
    float m = -CUDART_INF_F;   // running max (in log2 units)
    float l = 0.f;             // running denominator

    // scores carried as dot * (1/sqrt(64)) * log2(e); softmax via exp2 (EX2)
    const float sc = 0.125f * 1.44269504088896340736f;

    const int ntiles = 2 * qt + 2;   // key tiles covering keys [0, q0+BM)
    for (int kt = 0; kt < ntiles; kt++) {
        const int k0 = kt * BN;

        __syncthreads();  // previous tile's smem reads done before overwrite
        // ---- Stage K and V tiles: BN x DD floats each, float4 coalesced ----
        #pragma unroll
        for (int i = 0; i < (BN * DD / 4) / BM; i++) {   // 8 iters
            int idx = tid + i * BM;        // float4 index in tile
            int row = idx >> 4;            // 16 float4 per row
            int col = (idx & 15) * 4;
            size_t kbase = (((size_t)(b * SS + k0 + row) * 3 + 1) * HH + h) * DD + col;
            *reinterpret_cast<float4*>(ks + row * DD + col) =
                *reinterpret_cast<const float4*>(qkv + kbase);
            size_t vbase = (((size_t)(b * SS + k0 + row) * 3 + 2) * HH + h) * DD + col;
            *reinterpret_cast<float4*>(vs + row * DD + col) =
                *reinterpret_cast<const float4*>(qkv + vbase);
        }
        __syncthreads();

        // ---- Process 16-key chunks: scores -> online softmax -> PV ----
        #pragma unroll 1
        for (int jc = 0; jc < BN / CH; jc++) {
            float s[CH];
            #pragma unroll
            for (int jj = 0; jj < CH; jj++) s[jj] = 0.f;

            // s[jj] = q_row . k[jc*CH+jj]  (K reads are warp-broadcast LDS.128)
            #pragma unroll
            for (int d4 = 0; d4 < DD / 4; d4++) {
                float a0 = qs[tid * QS + 4 * d4 + 0];
                float a1 = qs[tid * QS + 4 * d4 + 1];
                float a2 = qs[tid * QS + 4 * d4 + 2];
                float a3 = qs[tid * QS + 4 * d4 + 3];
                #pragma unroll
                for (int jj = 0; jj < CH; jj++) {
                    float4 k4 = *reinterpret_cast<const float4*>(
                        ks + (jc * CH + jj) * DD + 4 * d4);
                    s[jj] += a0 * k4.x;
                    s[jj] += a1 * k4.y;
                    s[jj] += a2 * k4.z;
                    s[jj] += a3 * k4.w;
                }
            }

            // scale + causal mask + chunk max
            float mt = -CUDART_INF_F;
            #pragma unroll
            for (int jj = 0; jj < CH; jj++) {
                int jg = k0 + jc * CH + jj;
                s[jj] = (jg <= qi) ? s[jj] * sc : -CUDART_INF_F;
                mt = fmaxf(mt, s[jj]);
            }

            if (mt != -CUDART_INF_F) {   // skip fully-masked chunks (above diagonal)
                float mnew = fmaxf(m, mt);
                float corr = exp2f(m - mnew);   // m=-inf first time -> corr=0, acc=0 anyway
                float p[CH];
                float ps = 0.f;
                #pragma unroll
                for (int jj = 0; jj < CH; jj++) {
                    p[jj] = exp2f(s[jj] - mnew); // masked -> exp2(-inf)=0
                    ps += p[jj];
                }
                l = l * corr + ps;
                m = mnew;
                #pragma unroll
                for (int d = 0; d < DD; d++) acc[d] *= corr;
                #pragma unroll
                for (int jj = 0; jj < CH; jj++) {
                    #pragma unroll
                    for (int d4 = 0; d4 < DD / 4; d4++) {
                        float4 v4 = *reinterpret_cast<const float4*>(
                            vs + (jc * CH + jj) * DD + 4 * d4);
                        acc[4 * d4 + 0] += p[jj] * v4.x;
                        acc[4 * d4 + 1] += p[jj] * v4.y;
                        acc[4 * d4 + 2] += p[jj] * v4.z;
                        acc[4 * d4 + 3] += p[jj] * v4.w;
                    }
                }
            }
        }
    }

    // ---- Normalize and write out (b, qi, h, :) ----
    float inv = 1.0f / l;
    float4* dst = reinterpret_cast<float4*>(
        out + (((size_t)(b * SS + qi)) * HH + h) * DD);
    #pragma unroll
    for (int d4 = 0; d4 < DD / 4; d4++) {
        float4 o4;
        o4.x = acc[4 * d4 + 0] * inv;
        o4.y = acc[4 * d4 + 1] * inv;
        o4.z = acc[4 * d4 + 2] * inv;
        o4.w = acc[4 * d4 + 3] * inv;
        dst[d4] = o4;
    }
}

extern "C" void kernel_launch(void* const* d_in, const int* in_sizes, int n_in,
                              void* d_out, int out_size)
{
    const float* qkv = (const float*)d_in[0];
    float* out = (float*)d_out;

    const size_t smem = (size_t)(BM * QS + 2 * BN * DD) * sizeof(float);  // 66048 B
    cudaFuncSetAttribute(attn_fwd, cudaFuncAttributeMaxDynamicSharedMemorySize,
                         (int)smem);

    dim3 grid(SS / BM, HH, BB);
    attn_fwd<<<grid, BM, smem>>>(qkv, out);
}

// round 5
// speedup vs baseline: 4.7157x; 4.7157x over previous
#include <cuda_runtime.h>
#include <cuda_bf16.h>
#include <cstdint>

// qkv (B,S,3,H,D) fp32 -> out (B,S,H,D) fp32
#define BB 2
#define SS 2048
#define HH 16
#define DD 64
#define BM 64
#define BN 64
#define RS (3 * HH * DD)     // qkv row stride (elems) = 3072
#define PADS 72              // smem row stride in bf16 elems (144 B)

#define NELEM (BB * SS * 3 * HH * DD)   // 12,582,912

__device__ __nv_bfloat16 g_hi[NELEM];   // 25 MB
__device__ __nv_bfloat16 g_lo[NELEM];   // 25 MB

// ---- pre-pass: fp32 -> bf16 hi + bf16 lo residual (8 floats/thread) ----
__global__ void split_kernel(const float* __restrict__ qkv)
{
    int i = (blockIdx.x * blockDim.x + threadIdx.x) * 8;
    float4 va = *reinterpret_cast<const float4*>(qkv + i);
    float4 vb = *reinterpret_cast<const float4*>(qkv + i + 4);
    float f[8] = { va.x, va.y, va.z, va.w, vb.x, vb.y, vb.z, vb.w };
    uint32_t hw[4], lw[4];
    #pragma unroll
    for (int j = 0; j < 4; j++) {
        __nv_bfloat16 h0 = __float2bfloat16(f[2 * j]);
        __nv_bfloat16 h1 = __float2bfloat16(f[2 * j + 1]);
        __nv_bfloat162 hp = __halves2bfloat162(h0, h1);
        __nv_bfloat162 lp = __halves2bfloat162(
            __float2bfloat16(f[2 * j]     - __bfloat162float(h0)),
            __float2bfloat16(f[2 * j + 1] - __bfloat162float(h1)));
        hw[j] = *reinterpret_cast<uint32_t*>(&hp);
        lw[j] = *reinterpret_cast<uint32_t*>(&lp);
    }
    *reinterpret_cast<uint4*>(g_hi + i) = *reinterpret_cast<uint4*>(hw);
    *reinterpret_cast<uint4*>(g_lo + i) = *reinterpret_cast<uint4*>(lw);
}

// ---- smem elem offsets (bf16) ----
#define O_QHI 0
#define O_QLO 4608
#define O_KHI 9216
#define O_KLO 13824
#define O_VHI 18432
#define O_VLO 23040
#define SMEM_ELEMS 27648     // 55296 B

__device__ __forceinline__ uint32_t smem_u32(const void* p) {
    uint32_t a;
    asm("{ .reg .u64 t; cvta.to.shared.u64 t, %1; cvt.u32.u64 %0, t; }" : "=r"(a) : "l"(p));
    return a;
}
__device__ __forceinline__ float ex2f(float x) {
    float r; asm("ex2.approx.ftz.f32 %0, %1;" : "=f"(r) : "f"(x)); return r;
}

#define LDSM4(d0, d1, d2, d3, a) \
    asm volatile("ldmatrix.sync.aligned.m8n8.x4.shared.b16 {%0,%1,%2,%3}, [%4];" \
        : "=r"(d0), "=r"(d1), "=r"(d2), "=r"(d3) : "r"(a))
#define LDSM4T(d0, d1, d2, d3, a) \
    asm volatile("ldmatrix.sync.aligned.m8n8.x4.trans.shared.b16 {%0,%1,%2,%3}, [%4];" \
        : "=r"(d0), "=r"(d1), "=r"(d2), "=r"(d3) : "r"(a))

#define MMA(d, a, b0, b1) \
    asm volatile("mma.sync.aligned.m16n8k16.row.col.f32.bf16.bf16.f32 " \
        "{%0,%1,%2,%3}, {%4,%5,%6,%7}, {%8,%9}, {%0,%1,%2,%3};" \
        : "+f"((d)[0]), "+f"((d)[1]), "+f"((d)[2]), "+f"((d)[3]) \
        : "r"((a)[0]), "r"((a)[1]), "r"((a)[2]), "r"((a)[3]), "r"(b0), "r"(b1))

// copy 64x64 bf16 tile (global row stride RS) -> smem padded PADS, 16B chunks
__device__ __forceinline__ void stage(
    __nv_bfloat16* dst, const __nv_bfloat16* __restrict__ src, int tid)
{
    #pragma unroll
    for (int i = 0; i < 4; i++) {
        int c = tid + i * 128;          // 0..511 chunk id
        int row = c >> 3;
        int col = (c & 7) * 8;
        *reinterpret_cast<uint4*>(dst + row * PADS + col) =
            *reinterpret_cast<const uint4*>(src + (size_t)row * RS + col);
    }
}

__device__ __forceinline__ uint32_t pack_bf2(float a, float b) {
    __nv_bfloat162 t = __halves2bfloat162(__float2bfloat16(a), __float2bfloat16(b));
    return *reinterpret_cast<uint32_t*>(&t);
}

__global__ void __launch_bounds__(128) attn_fwd(float* __restrict__ out)
{
    extern __shared__ __nv_bfloat16 sm[];
    const uint32_t smb = smem_u32(sm);
    const int tid = threadIdx.x;
    const int wid = tid >> 5;
    const int lid = tid & 31;
    const int b = blockIdx.z, h = blockIdx.y;
    const int qt = (gridDim.x - 1) - blockIdx.x;    // heavy tiles first
    const int q0 = qt * BM;

    // ---- stage Q (hi/lo) ----
    const size_t qbase = (((size_t)(b * SS + q0) * 3 + 0) * HH + h) * DD;
    stage(sm + O_QHI, g_hi + qbase, tid);
    stage(sm + O_QLO, g_lo + qbase, tid);
    __syncthreads();

    // ---- load Q fragments (held for whole kernel) ----
    uint32_t qh[4][4], ql[4][4];
    {
        int r = 16 * wid + (lid & 15);
        int cb = (lid >> 4) * 8;
        #pragma unroll
        for (int ks = 0; ks < 4; ks++) {
            uint32_t ah = smb + (O_QHI + r * PADS + ks * 16 + cb) * 2;
            LDSM4(qh[ks][0], qh[ks][1], qh[ks][2], qh[ks][3], ah);
            uint32_t al = smb + (O_QLO + r * PADS + ks * 16 + cb) * 2;
            LDSM4(ql[ks][0], ql[ks][1], ql[ks][2], ql[ks][3], al);
        }
    }

    float O[8][4];
    #pragma unroll
    for (int j = 0; j < 8; j++)
        #pragma unroll
        for (int v = 0; v < 4; v++) O[j][v] = 0.f;
    float lsum0 = 0.f, lsum1 = 0.f;

    const float sc = 0.125f * 1.4426950408889634f;  // 1/sqrt(D) * log2(e)
    const int lrow0 = 16 * wid + (lid >> 2);        // local row of v0,v1
    const int colb = 2 * (lid & 3);
    const int ntiles = qt + 1;

    #pragma unroll 1
    for (int kt = 0; kt < ntiles; kt++) {
        const int k0 = kt * BN;
        if (kt) __syncthreads();
        const size_t kb = (((size_t)(b * SS + k0) * 3 + 1) * HH + h) * DD;
        const size_t vb = (((size_t)(b * SS + k0) * 3 + 2) * HH + h) * DD;
        stage(sm + O_KHI, g_hi + kb, tid);
        stage(sm + O_KLO, g_lo + kb, tid);
        stage(sm + O_VHI, g_hi + vb, tid);
        stage(sm + O_VLO, g_lo + vb, tid);
        __syncthreads();

        // ---- S = Q . K^T  (3-pass hi/lo) ----
        float S[8][4];
        #pragma unroll
        for (int j = 0; j < 8; j++)
            #pragma unroll
            for (int v = 0; v < 4; v++) S[j][v] = 0.f;

        {
            int r = lid & 15;
            int cb = (lid >> 4) * 8;
            #pragma unroll
            for (int ks = 0; ks < 4; ks++) {
                #pragma unroll
                for (int ng = 0; ng < 4; ng++) {
                    uint32_t kh0, kh1, kh2, kh3, kl0, kl1, kl2, kl3;
                    uint32_t ah = smb + (O_KHI + (16 * ng + r) * PADS + ks * 16 + cb) * 2;
                    LDSM4(kh0, kh1, kh2, kh3, ah);
                    uint32_t al = smb + (O_KLO + (16 * ng + r) * PADS + ks * 16 + cb) * 2;
                    LDSM4(kl0, kl1, kl2, kl3, al);
                    MMA(S[2 * ng],     qh[ks], kh0, kh2);
                    MMA(S[2 * ng],     qh[ks], kl0, kl2);
                    MMA(S[2 * ng],     ql[ks], kh0, kh2);
                    MMA(S[2 * ng + 1], qh[ks], kh1, kh3);
                    MMA(S[2 * ng + 1], qh[ks], kl1, kl3);
                    MMA(S[2 * ng + 1], ql[ks], kh1, kh3);
                }
            }
        }

        // ---- softmax (fixed max = 0) + PV, interleaved per 16-key step ----
        const bool diag = (kt == qt);
        #pragma unroll
        for (int vk = 0; vk < 4; vk++) {
            uint32_t ahi[4], alo[4];
            #pragma unroll
            for (int hf = 0; hf < 2; hf++) {
                int j = 2 * vk + hf;
                float p0 = ex2f(S[j][0] * sc);
                float p1 = ex2f(S[j][1] * sc);
                float p2 = ex2f(S[j][2] * sc);
                float p3 = ex2f(S[j][3] * sc);
                if (diag) {
                    int col = 8 * j + colb;         // local col (k0 == q0 on diag)
                    if (col > lrow0)     p0 = 0.f;
                    if (col + 1 > lrow0) p1 = 0.f;
                    if (col > lrow0 + 8)     p2 = 0.f;
                    if (col + 1 > lrow0 + 8) p3 = 0.f;
                }
                lsum0 += p0 + p1;
                lsum1 += p2 + p3;
                ahi[2 * hf + 0] = pack_bf2(p0, p1);
                ahi[2 * hf + 1] = pack_bf2(p2, p3);
                float r0 = p0 - __bfloat162float(__float2bfloat16(p0));
                float r1 = p1 - __bfloat162float(__float2bfloat16(p1));
                float r2 = p2 - __bfloat162float(__float2bfloat16(p2));
                float r3 = p3 - __bfloat162float(__float2bfloat16(p3));
                alo[2 * hf + 0] = pack_bf2(r0, r1);
                alo[2 * hf + 1] = pack_bf2(r2, r3);
            }
            // A-frag reg order: {row g k0-7, row g+8 k0-7, row g k8-15, row g+8 k8-15}
            uint32_t at_h[4] = { ahi[0], ahi[1], ahi[2], ahi[3] };
            uint32_t at_l[4] = { alo[0], alo[1], alo[2], alo[3] };

            int r = lid & 15;
            int cb = (lid >> 4) * 8;
            #pragma unroll
            for (int g2 = 0; g2 < 4; g2++) {
                uint32_t vh0, vh1, vh2, vh3, vl0, vl1, vl2, vl3;
                uint32_t ah = smb + (O_VHI + (16 * vk + r) * PADS + 16 * g2 + cb) * 2;
                LDSM4T(vh0, vh1, vh2, vh3, ah);
                uint32_t al = smb + (O_VLO + (16 * vk + r) * PADS + 16 * g2 + cb) * 2;
                LDSM4T(vl0, vl1, vl2, vl3, al);
                MMA(O[2 * g2],     at_h, vh0, vh1);
                MMA(O[2 * g2],     at_h, vl0, vl1);
                MMA(O[2 * g2],     at_l, vh0, vh1);
                MMA(O[2 * g2 + 1], at_h, vh2, vh3);
                MMA(O[2 * g2 + 1], at_h, vl2, vl3);
                MMA(O[2 * g2 + 1], at_l, vh2, vh3);
            }
        }
    }

    // ---- epilogue: row-sum reduce, normalize, store ----
    lsum0 += __shfl_xor_sync(0xffffffffu, lsum0, 1);
    lsum0 += __shfl_xor_sync(0xffffffffu, lsum0, 2);
    lsum1 += __shfl_xor_sync(0xffffffffu, lsum1, 1);
    lsum1 += __shfl_xor_sync(0xffffffffu, lsum1, 2);
    float inv0 = 1.0f / lsum0;
    float inv1 = 1.0f / lsum1;

    int grow0 = q0 + lrow0;
    int grow1 = grow0 + 8;
    float* o0 = out + (((size_t)(b * SS + grow0)) * HH + h) * DD;
    float* o1 = out + (((size_t)(b * SS + grow1)) * HH + h) * DD;
    #pragma unroll
    for (int j = 0; j < 8; j++) {
        int col = 8 * j + colb;
        float2 w0 = { O[j][0] * inv0, O[j][1] * inv0 };
        float2 w1 = { O[j][2] * inv1, O[j][3] * inv1 };
        *reinterpret_cast<float2*>(o0 + col) = w0;
        *reinterpret_cast<float2*>(o1 + col) = w1;
    }
}

extern "C" void kernel_launch(void* const* d_in, const int* in_sizes, int n_in,
                              void* d_out, int out_size)
{
    const float* qkv = (const float*)d_in[0];
    float* out = (float*)d_out;

    split_kernel<<<NELEM / (256 * 8), 256>>>(qkv);

    const int smem = SMEM_ELEMS * 2;   // 55296 B
    cudaFuncSetAttribute(attn_fwd, cudaFuncAttributeMaxDynamicSharedMemorySize, smem);
    dim3 grid(SS / BM, HH, BB);
    attn_fwd<<<grid, 128, smem>>>(out);
}